// round 14
// baseline (speedup 1.0000x reference)
#include <cuda_runtime.h>
#include <cuda_fp16.h>
#include <mma.h>
#include <math.h>

using namespace nvcuda;

#define Nn 100000
#define Ee 1600000
#define Dd 128
#define Hh 8
#define Ff 512
#define QKV 384
#define NBLK 391  // ceil(Nn/256)

// ---------------- scratch (static device globals; no allocation) ----------------
__device__ __half g_feat_h[(size_t)Nn * Dd];   // fp16 copy of feat (GEMM A)
__device__ __half g_q_h[(size_t)Nn * Dd];      // q fp16
__device__ __half g_kv_h[(size_t)Nn * 256];    // interleaved [k0..3 v0..3] per 4-dim group
__device__ __half g_wqkv_h[(size_t)Dd * QKV];  // [Wq | Wk | Wv] fp16
__device__ __half g_w1h[(size_t)Dd * Ff];
__device__ __half g_w2h[(size_t)Ff * Dd];
__device__ float  g_bqkv[QKV];
__device__ int    g_deg[Nn];                   // in-degree histogram
__device__ int    g_off[Nn + 1];               // CSR offsets
__device__ int    g_cursor[Nn];                // scatter cursors
__device__ int    g_bsum[512];                 // block sums for scan
__device__ int    g_csr_src[(size_t)Ee];       // src ids grouped by dst
__device__ float  g_rstn_f[(size_t)Nn * Dd];   // post-LN1 fp32 (residual for LN2)
__device__ __half g_rstn_h[(size_t)Nn * Dd];   // post-LN1 fp16 (FFN A)

// -------- init + weight conversion (every replay; deterministic) ---------------
__global__ void init_conv(const float* __restrict__ feat,
                          const float* __restrict__ Wq, const float* __restrict__ Wk,
                          const float* __restrict__ Wv, const float* __restrict__ bq,
                          const float* __restrict__ bk, const float* __restrict__ bv,
                          const float* __restrict__ W1, const float* __restrict__ W2) {
    const int i = blockIdx.x * blockDim.x + threadIdx.x;
    if (i < Nn * Dd) g_feat_h[i] = __float2half(feat[i]);
    if (i < Nn) g_deg[i] = 0;
    if (i < Dd * QKV) {
        const int r = i / QKV, c = i % QKV;
        float v;
        if (c < 128)      v = Wq[r * Dd + c];
        else if (c < 256) v = Wk[r * Dd + c - 128];
        else              v = Wv[r * Dd + c - 256];
        g_wqkv_h[i] = __float2half(v);
    }
    if (i < Dd * Ff) g_w1h[i] = __float2half(W1[i]);
    if (i < Ff * Dd) g_w2h[i] = __float2half(W2[i]);
    if (i < QKV) {
        float v;
        if (i < 128)      v = bq[i];
        else if (i < 256) v = bk[i - 128];
        else              v = bv[i - 256];
        g_bqkv[i] = v;
    }
}

// ---------------- cp.async helper ----------------
__device__ __forceinline__ void cp_async16(void* smem, const void* gmem, int sz) {
    const unsigned s = (unsigned)__cvta_generic_to_shared(smem);
    asm volatile("cp.async.cg.shared.global [%0], [%1], 16, %2;" ::
                     "r"(s), "l"(gmem), "r"(sz));
}

// ---------------- QKV GEMM (pipelined fp16, block 128x128, BK=32) ---------------
// writes split: col<128 -> g_q_h; [128,256) -> kv k-slots; [256,384) -> kv v-slots
struct StageBuf {
    __half As[2][128][40];
    __half Bs[2][32][136];
};
struct EpiBuf {
    float Cs[128][68];
};
union GSmem {
    StageBuf st;
    EpiBuf ep;
};

__global__ void __launch_bounds__(256) gemm_qkv(
    const __half* __restrict__ A, const __half* __restrict__ W,
    const float* __restrict__ bias, int M, int Nc, int K) {
    __shared__ GSmem sm;

    const int t = threadIdx.x;
    const int w = t >> 5;
    const int warp_m = w & 3;
    const int warp_n = w >> 2;
    const int bm = blockIdx.y * 128, bn = blockIdx.x * 128;

    wmma::fragment<wmma::accumulator, 16, 16, 16, float> cf[2][4];
#pragma unroll
    for (int i = 0; i < 2; i++)
#pragma unroll
        for (int j = 0; j < 4; j++) wmma::fill_fragment(cf[i][j], 0.f);

    const int nk = K >> 5;

#define LOAD_STAGE(S, KK)                                                           \
    {                                                                               \
        _Pragma("unroll") for (int i = 0; i < 2; i++) {                             \
            const int idx = t + i * 256;                                            \
            const int r = idx >> 2, c = (idx & 3) * 8;                              \
            cp_async16(&sm.st.As[S][r][c], &A[(size_t)(bm + r) * K + (KK) + c],     \
                       (bm + r) < M ? 16 : 0);                                      \
        }                                                                           \
        _Pragma("unroll") for (int i = 0; i < 2; i++) {                             \
            const int idx = t + i * 256;                                            \
            const int r = idx >> 4, c = (idx & 15) * 8;                             \
            cp_async16(&sm.st.Bs[S][r][c], &W[(size_t)((KK) + r) * Nc + bn + c],    \
                       16);                                                         \
        }                                                                           \
        asm volatile("cp.async.commit_group;");                                     \
    }

    LOAD_STAGE(0, 0)

    for (int s = 0; s < nk; s++) {
        if (s + 1 < nk) {
            LOAD_STAGE((s + 1) & 1, (s + 1) * 32)
            asm volatile("cp.async.wait_group 1;");
        } else {
            asm volatile("cp.async.wait_group 0;");
        }
        __syncthreads();

        const int buf = s & 1;
#pragma unroll
        for (int ks = 0; ks < 2; ks++) {
            const int k = ks * 16;
            wmma::fragment<wmma::matrix_a, 16, 16, 16, __half, wmma::row_major> af[2];
            wmma::fragment<wmma::matrix_b, 16, 16, 16, __half, wmma::row_major> bf[4];
#pragma unroll
            for (int i = 0; i < 2; i++)
                wmma::load_matrix_sync(af[i], &sm.st.As[buf][warp_m * 32 + i * 16][k], 40);
#pragma unroll
            for (int j = 0; j < 4; j++)
                wmma::load_matrix_sync(bf[j], &sm.st.Bs[buf][k][warp_n * 64 + j * 16], 136);
#pragma unroll
            for (int i = 0; i < 2; i++)
#pragma unroll
                for (int j = 0; j < 4; j++)
                    wmma::mma_sync(cf[i][j], af[i], bf[j], cf[i][j]);
        }
        __syncthreads();
    }
#undef LOAD_STAGE

#pragma unroll
    for (int h = 0; h < 2; h++) {
        if (warp_n == h) {
#pragma unroll
            for (int i = 0; i < 2; i++)
#pragma unroll
                for (int j = 0; j < 4; j++)
                    wmma::store_matrix_sync(&sm.ep.Cs[warp_m * 32 + i * 16][j * 16],
                                            cf[i][j], 68, wmma::mem_row_major);
        }
        __syncthreads();

#pragma unroll
        for (int i = 0; i < 8; i++) {
            const int idx = t + i * 256;
            const int row = idx >> 4;
            const int col = (idx & 15) * 4;
            const int gcol = bn + h * 64 + col;
            const int grow = bm + row;
            if (grow < M) {
                float c[4];
#pragma unroll
                for (int x = 0; x < 4; x++) c[x] = sm.ep.Cs[row][col + x] + bias[gcol + x];
                __half2 h01 = __floats2half2_rn(c[0], c[1]);
                __half2 h23 = __floats2half2_rn(c[2], c[3]);
                uint2 pk;
                pk.x = *(unsigned*)&h01;
                pk.y = *(unsigned*)&h23;
                if (gcol < 128) {
                    *(uint2*)&g_q_h[(size_t)grow * Dd + gcol] = pk;
                } else if (gcol < 256) {
                    const int c4 = gcol - 128;
                    *(uint2*)&g_kv_h[(size_t)grow * 256 + (c4 << 1)] = pk;
                } else {
                    const int c4 = gcol - 256;
                    *(uint2*)&g_kv_h[(size_t)grow * 256 + (c4 << 1) + 4] = pk;
                }
            }
        }
        __syncthreads();
    }
}

// ---------------- fused FFN: out = LN2(rstn + PReLU(rstn@W1+b1)@W2 + b2) --------
// block = 128 rows; 4 hidden chunks of 128; hid never leaves smem.
// NOTE: every 128x128 fp16 tile = 2048 x 16B chunks -> EIGHT iterations of 256 thr.
struct FFNSmem {
    __half As[128][136];    // rstn tile
    __half Hid[128][136];   // current hidden chunk (fp16)
    union {
        __half Wt[128][136];  // W1f / W2f tile
        struct {
            float Cs[128][68];
            float rsum[128], rsq[128], mu[128], rs[128];
        } e;
    } u;
};

__global__ void __launch_bounds__(256) ffn_fused(
    const float* __restrict__ res, const float* __restrict__ b1,
    const float* __restrict__ alpha, const float* __restrict__ b2,
    const float* __restrict__ lng, const float* __restrict__ lnb,
    float* __restrict__ C, int M) {
    extern __shared__ char dyn[];
    FFNSmem& sm = *(FFNSmem*)dyn;

    const int t = threadIdx.x;
    const int w = t >> 5;
    const int warp_m = w & 3;
    const int warp_n = w >> 2;
    const int bm = blockIdx.x * 128;

    // load rstn tile once: 128 rows x 128 halves = 2048 chunks (8 iters)
#pragma unroll
    for (int i = 0; i < 8; i++) {
        const int idx = t + i * 256;
        const int r = idx >> 4, c = (idx & 15) * 8;
        cp_async16(&sm.As[r][c], &g_rstn_h[(size_t)(bm + r) * Dd + c],
                   (bm + r) < M ? 16 : 0);
    }
    asm volatile("cp.async.commit_group;");

    wmma::fragment<wmma::accumulator, 16, 16, 16, float> cf[2][4];
#pragma unroll
    for (int i = 0; i < 2; i++)
#pragma unroll
        for (int j = 0; j < 4; j++) wmma::fill_fragment(cf[i][j], 0.f);

    for (int f = 0; f < 4; f++) {
        // load W1 chunk f: 128 rows x 128 halves (8 iters)
#pragma unroll
        for (int i = 0; i < 8; i++) {
            const int idx = t + i * 256;
            const int r = idx >> 4, c = (idx & 15) * 8;
            cp_async16(&sm.u.Wt[r][c], &g_w1h[(size_t)r * Ff + f * 128 + c], 16);
        }
        asm volatile("cp.async.commit_group;");
        asm volatile("cp.async.wait_group 0;");
        __syncthreads();

        // GEMM1: cg = As @ W1f (full K in smem, no inner syncs)
        wmma::fragment<wmma::accumulator, 16, 16, 16, float> cg[2][4];
#pragma unroll
        for (int i = 0; i < 2; i++)
#pragma unroll
            for (int j = 0; j < 4; j++) wmma::fill_fragment(cg[i][j], 0.f);
#pragma unroll
        for (int ks = 0; ks < 8; ks++) {
            const int k = ks * 16;
            wmma::fragment<wmma::matrix_a, 16, 16, 16, __half, wmma::row_major> af[2];
            wmma::fragment<wmma::matrix_b, 16, 16, 16, __half, wmma::row_major> bf[4];
#pragma unroll
            for (int i = 0; i < 2; i++)
                wmma::load_matrix_sync(af[i], &sm.As[warp_m * 32 + i * 16][k], 136);
#pragma unroll
            for (int j = 0; j < 4; j++)
                wmma::load_matrix_sync(bf[j], &sm.u.Wt[k][warp_n * 64 + j * 16], 136);
#pragma unroll
            for (int i = 0; i < 2; i++)
#pragma unroll
                for (int j = 0; j < 4; j++)
                    wmma::mma_sync(cg[i][j], af[i], bf[j], cg[i][j]);
        }
        __syncthreads();  // Wt reads done before Cs (alias) writes

        // bias + PReLU + fp16 convert -> Hid, via Cs in two halves
#pragma unroll
        for (int h = 0; h < 2; h++) {
            if (warp_n == h) {
#pragma unroll
                for (int i = 0; i < 2; i++)
#pragma unroll
                    for (int j = 0; j < 4; j++)
                        wmma::store_matrix_sync(&sm.u.e.Cs[warp_m * 32 + i * 16][j * 16],
                                                cg[i][j], 68, wmma::mem_row_major);
            }
            __syncthreads();
#pragma unroll
            for (int i = 0; i < 8; i++) {
                const int idx = t + i * 256;
                const int row = idx >> 4;
                const int col = (idx & 15) * 4;
                const int gcol = f * 128 + h * 64 + col;
                float c[4];
#pragma unroll
                for (int x = 0; x < 4; x++) {
                    c[x] = sm.u.e.Cs[row][col + x] + b1[gcol + x];
                    const float al = alpha[gcol + x];
                    c[x] = c[x] > 0.f ? c[x] : al * c[x];
                }
                __half2 h01 = __floats2half2_rn(c[0], c[1]);
                __half2 h23 = __floats2half2_rn(c[2], c[3]);
                uint2 pk;
                pk.x = *(unsigned*)&h01;
                pk.y = *(unsigned*)&h23;
                *(uint2*)&sm.Hid[row][h * 64 + col] = pk;
            }
            __syncthreads();
        }

        // load W2 chunk f: 128 rows x 128 halves (8 iters)
#pragma unroll
        for (int i = 0; i < 8; i++) {
            const int idx = t + i * 256;
            const int r = idx >> 4, c = (idx & 15) * 8;
            cp_async16(&sm.u.Wt[r][c], &g_w2h[(size_t)(f * 128 + r) * Dd + c], 16);
        }
        asm volatile("cp.async.commit_group;");
        asm volatile("cp.async.wait_group 0;");
        __syncthreads();

        // GEMM2: cf += Hid @ W2f
#pragma unroll
        for (int ks = 0; ks < 8; ks++) {
            const int k = ks * 16;
            wmma::fragment<wmma::matrix_a, 16, 16, 16, __half, wmma::row_major> af[2];
            wmma::fragment<wmma::matrix_b, 16, 16, 16, __half, wmma::row_major> bf[4];
#pragma unroll
            for (int i = 0; i < 2; i++)
                wmma::load_matrix_sync(af[i], &sm.Hid[warp_m * 32 + i * 16][k], 136);
#pragma unroll
            for (int j = 0; j < 4; j++)
                wmma::load_matrix_sync(bf[j], &sm.u.Wt[k][warp_n * 64 + j * 16], 136);
#pragma unroll
            for (int i = 0; i < 2; i++)
#pragma unroll
                for (int j = 0; j < 4; j++)
                    wmma::mma_sync(cf[i][j], af[i], bf[j], cf[i][j]);
        }
        __syncthreads();  // before next f overwrites Wt / Hid
    }

    // ---------------- final epilogue: +b2 +res, row-LN, fp32 out ----------------
    float vals[2][8][4];
    if (t < 128) { sm.u.e.rsum[t] = 0.f; sm.u.e.rsq[t] = 0.f; }
    __syncthreads();

#pragma unroll
    for (int h = 0; h < 2; h++) {
        if (warp_n == h) {
#pragma unroll
            for (int i = 0; i < 2; i++)
#pragma unroll
                for (int j = 0; j < 4; j++)
                    wmma::store_matrix_sync(&sm.u.e.Cs[warp_m * 32 + i * 16][j * 16],
                                            cf[i][j], 68, wmma::mem_row_major);
        }
        __syncthreads();
#pragma unroll
        for (int i = 0; i < 8; i++) {
            const int idx = t + i * 256;
            const int row = idx >> 4;
            const int col = (idx & 15) * 4;
            const int gcol = h * 64 + col;
            const int grow = bm + row;
            float c[4] = {0.f, 0.f, 0.f, 0.f};
            if (grow < M) {
                const float4 r4 = *(const float4*)&res[(size_t)grow * Dd + gcol];
#pragma unroll
                for (int x = 0; x < 4; x++)
                    c[x] = sm.u.e.Cs[row][col + x] + b2[gcol + x];
                c[0] += r4.x; c[1] += r4.y; c[2] += r4.z; c[3] += r4.w;
            }
#pragma unroll
            for (int x = 0; x < 4; x++) vals[h][i][x] = c[x];
            float ps = c[0] + c[1] + c[2] + c[3];
            float pq = c[0] * c[0] + c[1] * c[1] + c[2] * c[2] + c[3] * c[3];
#pragma unroll
            for (int o = 1; o < 16; o <<= 1) {
                ps += __shfl_xor_sync(0xffffffffu, ps, o, 16);
                pq += __shfl_xor_sync(0xffffffffu, pq, o, 16);
            }
            if ((t & 15) == 0) {
                sm.u.e.rsum[row] += ps;
                sm.u.e.rsq[row] += pq;
            }
        }
        __syncthreads();
    }

    if (t < 128) {
        const float mu = sm.u.e.rsum[t] * (1.f / 128.f);
        const float var = sm.u.e.rsq[t] * (1.f / 128.f) - mu * mu;
        sm.u.e.mu[t] = mu;
        sm.u.e.rs[t] = rsqrtf(var + 1e-5f);
    }
    __syncthreads();
#pragma unroll
    for (int h = 0; h < 2; h++)
#pragma unroll
        for (int i = 0; i < 8; i++) {
            const int idx = t + i * 256;
            const int row = idx >> 4;
            const int col = (idx & 15) * 4;
            const int gcol = h * 64 + col;
            const int grow = bm + row;
            if (grow >= M) continue;
            const float mu = sm.u.e.mu[row], rsg = sm.u.e.rs[row];
            float o[4];
#pragma unroll
            for (int x = 0; x < 4; x++)
                o[x] = (vals[h][i][x] - mu) * rsg * lng[gcol + x] + lnb[gcol + x];
            *(float4*)&C[(size_t)grow * Dd + gcol] = make_float4(o[0], o[1], o[2], o[3]);
        }
}

// ---------------- degree histogram ----------------
__global__ void deg_count(const int* __restrict__ dst) {
    const int e = blockIdx.x * blockDim.x + threadIdx.x;
    if (e < Ee) atomicAdd(&g_deg[dst[e]], 1);
}

// ---------------- scan kernels (exclusive prefix sum of deg) -------------------
__global__ void scanA() {
    __shared__ int smv[256];
    const int t = threadIdx.x;
    const int i = blockIdx.x * 256 + t;
    const int v = (i < Nn) ? g_deg[i] : 0;
    smv[t] = v;
    __syncthreads();
    for (int o = 1; o < 256; o <<= 1) {
        int x = smv[t];
        if (t >= o) x += smv[t - o];
        __syncthreads();
        smv[t] = x;
        __syncthreads();
    }
    if (i < Nn) g_off[i] = smv[t] - v;
    if (t == 255) g_bsum[blockIdx.x] = smv[255];
}
__global__ void scanB() {
    __shared__ int smv[512];
    const int t = threadIdx.x;
    const int v = (t < NBLK) ? g_bsum[t] : 0;
    smv[t] = v;
    __syncthreads();
    for (int o = 1; o < 512; o <<= 1) {
        int x = smv[t];
        if (t >= o) x += smv[t - o];
        __syncthreads();
        smv[t] = x;
        __syncthreads();
    }
    if (t < NBLK) g_bsum[t] = smv[t] - v;
}
__global__ void scanC() {
    const int i = blockIdx.x * blockDim.x + threadIdx.x;
    if (i < Nn) {
        const int o = g_off[i] + g_bsum[i >> 8];
        g_off[i] = o;
        g_cursor[i] = o;
    }
    if (i == 0) g_off[Nn] = Ee;
}

// ---------------- scatter: build dst-grouped src lists -------------------------
__global__ void scatter_k(const int* __restrict__ src, const int* __restrict__ dst) {
    const int e = blockIdx.x * blockDim.x + threadIdx.x;
    if (e >= Ee) return;
    const int p = atomicAdd(&g_cursor[dst[e]], 1);
    g_csr_src[p] = src[e];
}

// ---------------- fused gather: score + softmax-aggregate + LN1 ----------------
#define EDGE_BODY(KV, A0, A1, A2, A3, DS)                                      \
    {                                                                          \
        const float2 k01 = __half22float2(*(const __half2*)&KV.x);             \
        const float2 k23 = __half22float2(*(const __half2*)&KV.y);             \
        float p = k01.x * q01.x + k01.y * q01.y + k23.x * q23.x + k23.y * q23.y; \
        p += __shfl_xor_sync(0xffffffffu, p, 1);                               \
        p += __shfl_xor_sync(0xffffffffu, p, 2);                               \
        const float ee = __expf(p * 0.08838834764831845f);                     \
        const float2 v01 = __half22float2(*(const __half2*)&KV.z);             \
        const float2 v23 = __half22float2(*(const __half2*)&KV.w);             \
        A0 += ee * v01.x; A1 += ee * v01.y;                                    \
        A2 += ee * v23.x; A3 += ee * v23.y;                                    \
        DS += ee;                                                              \
    }

__global__ void __launch_bounds__(128) pass_fused(
    const float* __restrict__ feat, const float* __restrict__ lng,
    const float* __restrict__ lnb) {
    const int t = threadIdx.x;
    const int lane = t & 31;
    const int n = blockIdx.x * 4 + (t >> 5);
    if (n >= Nn) return;
    const int base = g_off[n];
    const int degn = g_deg[n];

    const uint2 qr = *(const uint2*)&g_q_h[(size_t)n * Dd + lane * 4];
    const float2 q01 = __half22float2(*(const __half2*)&qr.x);
    const float2 q23 = __half22float2(*(const __half2*)&qr.y);

    float a0 = 0.f, a1 = 0.f, a2 = 0.f, a3 = 0.f, dsa = 0.f;
    float b0 = 0.f, b1 = 0.f, b2 = 0.f, b3 = 0.f, dsb = 0.f;

    for (int j0 = 0; j0 < degn; j0 += 32) {
        int srec = 0;
        if (j0 + lane < degn) srec = g_csr_src[base + j0 + lane];
        const int cnt = min(32, degn - j0);
        int j = 0;
        for (; j + 2 <= cnt; j += 2) {
            const int s0 = __shfl_sync(0xffffffffu, srec, j);
            const int s1 = __shfl_sync(0xffffffffu, srec, j + 1);
            const uint4 kv0 = *(const uint4*)&g_kv_h[(size_t)s0 * 256 + lane * 8];
            const uint4 kv1 = *(const uint4*)&g_kv_h[(size_t)s1 * 256 + lane * 8];
            EDGE_BODY(kv0, a0, a1, a2, a3, dsa)
            EDGE_BODY(kv1, b0, b1, b2, b3, dsb)
        }
        if (j < cnt) {
            const int s0 = __shfl_sync(0xffffffffu, srec, j);
            const uint4 kv0 = *(const uint4*)&g_kv_h[(size_t)s0 * 256 + lane * 8];
            EDGE_BODY(kv0, a0, a1, a2, a3, dsa)
        }
    }
    a0 += b0; a1 += b1; a2 += b2; a3 += b3;
    const float dsum = dsa + dsb;

    const float inv = degn ? 1.f / dsum : 0.f;
    const float4 f = *(const float4*)&feat[(size_t)n * Dd + lane * 4];
    const float m0 = f.x + a0 * inv;
    const float m1 = f.y + a1 * inv;
    const float m2 = f.z + a2 * inv;
    const float m3 = f.w + a3 * inv;

    float s = m0 + m1 + m2 + m3;
    float s2 = m0 * m0 + m1 * m1 + m2 * m2 + m3 * m3;
#pragma unroll
    for (int o = 16; o > 0; o >>= 1) {
        s += __shfl_xor_sync(0xffffffffu, s, o);
        s2 += __shfl_xor_sync(0xffffffffu, s2, o);
    }
    const float mu = s * (1.f / 128.f);
    const float var = s2 * (1.f / 128.f) - mu * mu;
    const float rs = rsqrtf(var + 1e-5f);

    const float4 gg = *(const float4*)&lng[lane * 4];
    const float4 bb = *(const float4*)&lnb[lane * 4];
    const float y0 = (m0 - mu) * rs * gg.x + bb.x;
    const float y1 = (m1 - mu) * rs * gg.y + bb.y;
    const float y2 = (m2 - mu) * rs * gg.z + bb.z;
    const float y3 = (m3 - mu) * rs * gg.w + bb.w;

    *(float4*)&g_rstn_f[(size_t)n * Dd + lane * 4] = make_float4(y0, y1, y2, y3);
    __half2 h01 = __floats2half2_rn(y0, y1);
    __half2 h23 = __floats2half2_rn(y2, y3);
    uint2 pk;
    pk.x = *(unsigned*)&h01;
    pk.y = *(unsigned*)&h23;
    *(uint2*)&g_rstn_h[(size_t)n * Dd + lane * 4] = pk;
}

// ---------------- launch ----------------
extern "C" void kernel_launch(void* const* d_in, const int* in_sizes, int n_in,
                              void* d_out, int out_size) {
    const float* feat  = (const float*)d_in[0];
    const int*   src   = (const int*)d_in[1];
    const int*   dst   = (const int*)d_in[2];
    const float* Wq    = (const float*)d_in[3];
    const float* bq    = (const float*)d_in[4];
    const float* Wk    = (const float*)d_in[5];
    const float* bk    = (const float*)d_in[6];
    const float* Wv    = (const float*)d_in[7];
    const float* bv    = (const float*)d_in[8];
    const float* ln_g  = (const float*)d_in[9];
    const float* ln_b  = (const float*)d_in[10];
    const float* W1    = (const float*)d_in[11];
    const float* b1    = (const float*)d_in[12];
    const float* alpha = (const float*)d_in[13];
    const float* W2    = (const float*)d_in[14];
    const float* b2    = (const float*)d_in[15];
    float* out = (float*)d_out;

    __half *pfh, *pwqkv;
    float *pbqkv, *prstf;
    cudaGetSymbolAddress((void**)&pfh, g_feat_h);
    cudaGetSymbolAddress((void**)&pwqkv, g_wqkv_h);
    cudaGetSymbolAddress((void**)&pbqkv, g_bqkv);
    cudaGetSymbolAddress((void**)&prstf, g_rstn_f);

    const int MB = (Nn + 127) / 128;  // 782
    const int FFN_SMEM = (int)sizeof(FFNSmem);
    cudaFuncSetAttribute(ffn_fused, cudaFuncAttributeMaxDynamicSharedMemorySize,
                         FFN_SMEM);

    init_conv<<<(Nn * Dd + 255) / 256, 256>>>(feat, Wq, Wk, Wv, bq, bk, bv, W1, W2);
    deg_count<<<(Ee + 255) / 256, 256>>>(dst);

    // fused QKV projection: [Nn,128] @ [128,384] -> split fp16 q / interleaved kv
    gemm_qkv<<<dim3(QKV / 128, MB), 256>>>(pfh, pwqkv, pbqkv, Nn, QKV, Dd);

    scanA<<<NBLK, 256>>>();
    scanB<<<1, 512>>>();
    scanC<<<(Nn + 255) / 256, 256>>>();
    scatter_k<<<(Ee + 255) / 256, 256>>>(src, dst);

    // fused score + aggregate + LN1 (no atomics, one edge sweep)
    pass_fused<<<(Nn + 3) / 4, 128>>>(feat, ln_g, ln_b);

    // fused FFN1+FFN2+LN2 -> out (hid never leaves smem)
    ffn_fused<<<MB, 256, FFN_SMEM>>>(prstf, b1, alpha, b2, ln_g, ln_b, out, Nn);
}

// round 15
// speedup vs baseline: 1.0866x; 1.0866x over previous
#include <cuda_runtime.h>
#include <cuda_fp16.h>
#include <mma.h>
#include <math.h>

using namespace nvcuda;

#define Nn 100000
#define Ee 1600000
#define Dd 128
#define Hh 8
#define Ff 512
#define QKV 384
#define NBLK 391  // ceil(Nn/256)

// ---------------- scratch (static device globals; no allocation) ----------------
__device__ __half g_feat_h[(size_t)Nn * Dd];   // fp16 copy of feat (GEMM A)
__device__ __half g_q_h[(size_t)Nn * Dd];      // q fp16
__device__ __half g_kv_h[(size_t)Nn * 256];    // interleaved [k0..3 v0..3] per 4-dim group
__device__ __half g_wqkv_h[(size_t)Dd * QKV];  // [Wq | Wk | Wv] fp16
__device__ __half g_w1h[(size_t)Dd * Ff];
__device__ __half g_w2h[(size_t)Ff * Dd];
__device__ float  g_bqkv[QKV];
__device__ int    g_deg[Nn];                   // in-degree histogram
__device__ int    g_off[Nn + 1];               // CSR offsets
__device__ int    g_cursor[Nn];                // scatter cursors
__device__ int    g_bsum[512];                 // block sums for scan
__device__ int    g_csr_src[(size_t)Ee];       // src ids grouped by dst
__device__ float  g_rstn_f[(size_t)Nn * Dd];   // post-LN1 fp32 (residual for LN2)
__device__ __half g_rstn_h[(size_t)Nn * Dd];   // post-LN1 fp16 (FFN1 A)
__device__ __half g_hid_h[(size_t)Nn * Ff];    // FFN hidden fp16 (FFN2 A)

// -------- init + weight conversion (every replay; deterministic) ---------------
__global__ void init_conv(const float* __restrict__ feat,
                          const float* __restrict__ Wq, const float* __restrict__ Wk,
                          const float* __restrict__ Wv, const float* __restrict__ bq,
                          const float* __restrict__ bk, const float* __restrict__ bv,
                          const float* __restrict__ W1, const float* __restrict__ W2) {
    const int i = blockIdx.x * blockDim.x + threadIdx.x;
    if (i < Nn * Dd) g_feat_h[i] = __float2half(feat[i]);
    if (i < Dd * QKV) {
        const int r = i / QKV, c = i % QKV;
        float v;
        if (c < 128)      v = Wq[r * Dd + c];
        else if (c < 256) v = Wk[r * Dd + c - 128];
        else              v = Wv[r * Dd + c - 256];
        g_wqkv_h[i] = __float2half(v);
    }
    if (i < Dd * Ff) g_w1h[i] = __float2half(W1[i]);
    if (i < Ff * Dd) g_w2h[i] = __float2half(W2[i]);
    if (i < QKV) {
        float v;
        if (i < 128)      v = bq[i];
        else if (i < 256) v = bk[i - 128];
        else              v = bv[i - 256];
        g_bqkv[i] = v;
    }
}

// ---------------- cp.async helper ----------------
__device__ __forceinline__ void cp_async16(void* smem, const void* gmem, int sz) {
    const unsigned s = (unsigned)__cvta_generic_to_shared(smem);
    asm volatile("cp.async.cg.shared.global [%0], [%1], 16, %2;" ::
                     "r"(s), "l"(gmem), "r"(sz));
}

// ---------------- pipelined fp16 GEMM: C = A[M,K] @ W[K,Nc] + bias ----------------
// Block tile 128x128, BK=32, 2-stage cp.async, 8 warps (warp tile 32x64). fp32 accum.
// MODE 1: PReLU -> fp16 C    MODE 3: +res(fp32) -> row-LN -> fp32 C (Nc==128)
// MODE 4: qkv split: col<128 -> g_q_h; [128,256) -> kv k-slots; [256,384) -> v-slots
struct StageBuf {
    __half As[2][128][40];
    __half Bs[2][32][136];
};
struct EpiBuf {
    float Cs[128][68];
    float rsum[128], rsq[128], mu[128], rs[128];
};
union GSmem {
    StageBuf st;
    EpiBuf ep;
};

template <int MODE>
__global__ void __launch_bounds__(256) gemm_h(
    const __half* __restrict__ A, const __half* __restrict__ W,
    const float* __restrict__ bias, const float* __restrict__ alpha,
    const float* __restrict__ res, const float* __restrict__ lng,
    const float* __restrict__ lnb, void* __restrict__ Cout,
    int M, int Nc, int K) {
    __shared__ GSmem sm;

    const int t = threadIdx.x;
    const int w = t >> 5;
    const int warp_m = w & 3;
    const int warp_n = w >> 2;
    const int bm = blockIdx.y * 128, bn = blockIdx.x * 128;

    wmma::fragment<wmma::accumulator, 16, 16, 16, float> cf[2][4];
#pragma unroll
    for (int i = 0; i < 2; i++)
#pragma unroll
        for (int j = 0; j < 4; j++) wmma::fill_fragment(cf[i][j], 0.f);

    const int nk = K >> 5;

#define LOAD_STAGE(S, KK)                                                           \
    {                                                                               \
        _Pragma("unroll") for (int i = 0; i < 2; i++) {                             \
            const int idx = t + i * 256;                                            \
            const int r = idx >> 2, c = (idx & 3) * 8;                              \
            cp_async16(&sm.st.As[S][r][c], &A[(size_t)(bm + r) * K + (KK) + c],     \
                       (bm + r) < M ? 16 : 0);                                      \
        }                                                                           \
        _Pragma("unroll") for (int i = 0; i < 2; i++) {                             \
            const int idx = t + i * 256;                                            \
            const int r = idx >> 4, c = (idx & 15) * 8;                             \
            cp_async16(&sm.st.Bs[S][r][c], &W[(size_t)((KK) + r) * Nc + bn + c],    \
                       16);                                                         \
        }                                                                           \
        asm volatile("cp.async.commit_group;");                                     \
    }

    LOAD_STAGE(0, 0)

    for (int s = 0; s < nk; s++) {
        if (s + 1 < nk) {
            LOAD_STAGE((s + 1) & 1, (s + 1) * 32)
            asm volatile("cp.async.wait_group 1;");
        } else {
            asm volatile("cp.async.wait_group 0;");
        }
        __syncthreads();

        const int buf = s & 1;
#pragma unroll
        for (int ks = 0; ks < 2; ks++) {
            const int k = ks * 16;
            wmma::fragment<wmma::matrix_a, 16, 16, 16, __half, wmma::row_major> af[2];
            wmma::fragment<wmma::matrix_b, 16, 16, 16, __half, wmma::row_major> bf[4];
#pragma unroll
            for (int i = 0; i < 2; i++)
                wmma::load_matrix_sync(af[i], &sm.st.As[buf][warp_m * 32 + i * 16][k], 40);
#pragma unroll
            for (int j = 0; j < 4; j++)
                wmma::load_matrix_sync(bf[j], &sm.st.Bs[buf][k][warp_n * 64 + j * 16], 136);
#pragma unroll
            for (int i = 0; i < 2; i++)
#pragma unroll
                for (int j = 0; j < 4; j++)
                    wmma::mma_sync(cf[i][j], af[i], bf[j], cf[i][j]);
        }
        __syncthreads();
    }

    // ---------------- epilogue ----------------
    float vals[2][8][4];  // live only for MODE 3

    if (MODE == 3) {
        if (t < 128) { sm.ep.rsum[t] = 0.f; sm.ep.rsq[t] = 0.f; }
        __syncthreads();
    }

#pragma unroll
    for (int h = 0; h < 2; h++) {
        if (warp_n == h) {
#pragma unroll
            for (int i = 0; i < 2; i++)
#pragma unroll
                for (int j = 0; j < 4; j++)
                    wmma::store_matrix_sync(&sm.ep.Cs[warp_m * 32 + i * 16][j * 16],
                                            cf[i][j], 68, wmma::mem_row_major);
        }
        __syncthreads();

#pragma unroll
        for (int i = 0; i < 8; i++) {
            const int idx = t + i * 256;
            const int row = idx >> 4;
            const int col = (idx & 15) * 4;
            const int gcol = bn + h * 64 + col;
            const int grow = bm + row;
            float c[4];
#pragma unroll
            for (int x = 0; x < 4; x++) c[x] = sm.ep.Cs[row][col + x] + bias[gcol + x];
            if (MODE == 1) {
#pragma unroll
                for (int x = 0; x < 4; x++) {
                    const float al = alpha[gcol + x];
                    c[x] = c[x] > 0.f ? c[x] : al * c[x];
                }
            }
            if (MODE == 3 && grow < M) {
                const float4 r4 = *(const float4*)&res[(size_t)grow * Nc + gcol];
                c[0] += r4.x; c[1] += r4.y; c[2] += r4.z; c[3] += r4.w;
            }
            if (MODE == 1) {
                if (grow < M) {
                    __half2 h01 = __floats2half2_rn(c[0], c[1]);
                    __half2 h23 = __floats2half2_rn(c[2], c[3]);
                    uint2 pk;
                    pk.x = *(unsigned*)&h01;
                    pk.y = *(unsigned*)&h23;
                    *(uint2*)&((__half*)Cout)[(size_t)grow * Nc + gcol] = pk;
                }
            } else if (MODE == 4) {
                if (grow < M) {
                    __half2 h01 = __floats2half2_rn(c[0], c[1]);
                    __half2 h23 = __floats2half2_rn(c[2], c[3]);
                    uint2 pk;
                    pk.x = *(unsigned*)&h01;
                    pk.y = *(unsigned*)&h23;
                    if (gcol < 128) {
                        *(uint2*)&g_q_h[(size_t)grow * Dd + gcol] = pk;
                    } else if (gcol < 256) {
                        const int c4 = gcol - 128;
                        *(uint2*)&g_kv_h[(size_t)grow * 256 + (c4 << 1)] = pk;
                    } else {
                        const int c4 = gcol - 256;
                        *(uint2*)&g_kv_h[(size_t)grow * 256 + (c4 << 1) + 4] = pk;
                    }
                }
            } else if (MODE == 3) {
#pragma unroll
                for (int x = 0; x < 4; x++) vals[h][i][x] = c[x];
                float ps = c[0] + c[1] + c[2] + c[3];
                float pq = c[0] * c[0] + c[1] * c[1] + c[2] * c[2] + c[3] * c[3];
#pragma unroll
                for (int o = 1; o < 16; o <<= 1) {
                    ps += __shfl_xor_sync(0xffffffffu, ps, o, 16);
                    pq += __shfl_xor_sync(0xffffffffu, pq, o, 16);
                }
                if ((t & 15) == 0) {
                    sm.ep.rsum[row] += ps;
                    sm.ep.rsq[row] += pq;
                }
            }
        }
        __syncthreads();
    }

    if (MODE == 3) {
        if (t < 128) {
            const float mu = sm.ep.rsum[t] * (1.f / 128.f);
            const float var = sm.ep.rsq[t] * (1.f / 128.f) - mu * mu;
            sm.ep.mu[t] = mu;
            sm.ep.rs[t] = rsqrtf(var + 1e-5f);
        }
        __syncthreads();
        float* C = (float*)Cout;
#pragma unroll
        for (int h = 0; h < 2; h++)
#pragma unroll
            for (int i = 0; i < 8; i++) {
                const int idx = t + i * 256;
                const int row = idx >> 4;
                const int col = (idx & 15) * 4;
                const int gcol = h * 64 + col;  // bn == 0 in MODE 3
                const int grow = bm + row;
                if (grow >= M) continue;
                const float mu = sm.ep.mu[row], rsg = sm.ep.rs[row];
                float o[4];
#pragma unroll
                for (int x = 0; x < 4; x++)
                    o[x] = (vals[h][i][x] - mu) * rsg * lng[gcol + x] + lnb[gcol + x];
                *(float4*)&C[(size_t)grow * 128 + gcol] =
                    make_float4(o[0], o[1], o[2], o[3]);
            }
    }
#undef LOAD_STAGE
}

// ---------------- CSR chain (independent of qkv; runs on side stream) ----------
__global__ void zero_deg() {
    const int i = blockIdx.x * blockDim.x + threadIdx.x;
    if (i < Nn) g_deg[i] = 0;
}
__global__ void deg_count(const int* __restrict__ dst) {
    const int e = blockIdx.x * blockDim.x + threadIdx.x;
    if (e < Ee) atomicAdd(&g_deg[dst[e]], 1);
}
__global__ void scanA() {
    __shared__ int smv[256];
    const int t = threadIdx.x;
    const int i = blockIdx.x * 256 + t;
    const int v = (i < Nn) ? g_deg[i] : 0;
    smv[t] = v;
    __syncthreads();
    for (int o = 1; o < 256; o <<= 1) {
        int x = smv[t];
        if (t >= o) x += smv[t - o];
        __syncthreads();
        smv[t] = x;
        __syncthreads();
    }
    if (i < Nn) g_off[i] = smv[t] - v;
    if (t == 255) g_bsum[blockIdx.x] = smv[255];
}
__global__ void scanB() {
    __shared__ int smv[512];
    const int t = threadIdx.x;
    const int v = (t < NBLK) ? g_bsum[t] : 0;
    smv[t] = v;
    __syncthreads();
    for (int o = 1; o < 512; o <<= 1) {
        int x = smv[t];
        if (t >= o) x += smv[t - o];
        __syncthreads();
        smv[t] = x;
        __syncthreads();
    }
    if (t < NBLK) g_bsum[t] = smv[t] - v;
}
__global__ void scanC() {
    const int i = blockIdx.x * blockDim.x + threadIdx.x;
    if (i < Nn) {
        const int o = g_off[i] + g_bsum[i >> 8];
        g_off[i] = o;
        g_cursor[i] = o;
    }
    if (i == 0) g_off[Nn] = Ee;
}
__global__ void scatter_k(const int* __restrict__ src, const int* __restrict__ dst) {
    const int e = blockIdx.x * blockDim.x + threadIdx.x;
    if (e >= Ee) return;
    const int p = atomicAdd(&g_cursor[dst[e]], 1);
    g_csr_src[p] = src[e];
}

// ---------------- fused gather: score + softmax-aggregate + LN1 ----------------
#define EDGE_BODY(KV, A0, A1, A2, A3, DS)                                      \
    {                                                                          \
        const float2 k01 = __half22float2(*(const __half2*)&KV.x);             \
        const float2 k23 = __half22float2(*(const __half2*)&KV.y);             \
        float p = k01.x * q01.x + k01.y * q01.y + k23.x * q23.x + k23.y * q23.y; \
        p += __shfl_xor_sync(0xffffffffu, p, 1);                               \
        p += __shfl_xor_sync(0xffffffffu, p, 2);                               \
        const float ee = __expf(p * 0.08838834764831845f);                     \
        const float2 v01 = __half22float2(*(const __half2*)&KV.z);             \
        const float2 v23 = __half22float2(*(const __half2*)&KV.w);             \
        A0 += ee * v01.x; A1 += ee * v01.y;                                    \
        A2 += ee * v23.x; A3 += ee * v23.y;                                    \
        DS += ee;                                                              \
    }

__global__ void __launch_bounds__(128) pass_fused(
    const float* __restrict__ feat, const float* __restrict__ lng,
    const float* __restrict__ lnb) {
    const int t = threadIdx.x;
    const int lane = t & 31;
    const int n = blockIdx.x * 4 + (t >> 5);
    if (n >= Nn) return;
    const int base = g_off[n];
    const int degn = g_deg[n];

    const uint2 qr = *(const uint2*)&g_q_h[(size_t)n * Dd + lane * 4];
    const float2 q01 = __half22float2(*(const __half2*)&qr.x);
    const float2 q23 = __half22float2(*(const __half2*)&qr.y);

    float a0 = 0.f, a1 = 0.f, a2 = 0.f, a3 = 0.f, dsa = 0.f;
    float b0 = 0.f, b1 = 0.f, b2 = 0.f, b3 = 0.f, dsb = 0.f;

    for (int j0 = 0; j0 < degn; j0 += 32) {
        int srec = 0;
        if (j0 + lane < degn) srec = g_csr_src[base + j0 + lane];
        const int cnt = min(32, degn - j0);
        int j = 0;
        for (; j + 2 <= cnt; j += 2) {
            const int s0 = __shfl_sync(0xffffffffu, srec, j);
            const int s1 = __shfl_sync(0xffffffffu, srec, j + 1);
            const uint4 kv0 = *(const uint4*)&g_kv_h[(size_t)s0 * 256 + lane * 8];
            const uint4 kv1 = *(const uint4*)&g_kv_h[(size_t)s1 * 256 + lane * 8];
            EDGE_BODY(kv0, a0, a1, a2, a3, dsa)
            EDGE_BODY(kv1, b0, b1, b2, b3, dsb)
        }
        if (j < cnt) {
            const int s0 = __shfl_sync(0xffffffffu, srec, j);
            const uint4 kv0 = *(const uint4*)&g_kv_h[(size_t)s0 * 256 + lane * 8];
            EDGE_BODY(kv0, a0, a1, a2, a3, dsa)
        }
    }
    a0 += b0; a1 += b1; a2 += b2; a3 += b3;
    const float dsum = dsa + dsb;

    const float inv = degn ? 1.f / dsum : 0.f;
    const float4 f = *(const float4*)&feat[(size_t)n * Dd + lane * 4];
    const float m0 = f.x + a0 * inv;
    const float m1 = f.y + a1 * inv;
    const float m2 = f.z + a2 * inv;
    const float m3 = f.w + a3 * inv;

    float s = m0 + m1 + m2 + m3;
    float s2 = m0 * m0 + m1 * m1 + m2 * m2 + m3 * m3;
#pragma unroll
    for (int o = 16; o > 0; o >>= 1) {
        s += __shfl_xor_sync(0xffffffffu, s, o);
        s2 += __shfl_xor_sync(0xffffffffu, s2, o);
    }
    const float mu = s * (1.f / 128.f);
    const float var = s2 * (1.f / 128.f) - mu * mu;
    const float rs = rsqrtf(var + 1e-5f);

    const float4 gg = *(const float4*)&lng[lane * 4];
    const float4 bb = *(const float4*)&lnb[lane * 4];
    const float y0 = (m0 - mu) * rs * gg.x + bb.x;
    const float y1 = (m1 - mu) * rs * gg.y + bb.y;
    const float y2 = (m2 - mu) * rs * gg.z + bb.z;
    const float y3 = (m3 - mu) * rs * gg.w + bb.w;

    *(float4*)&g_rstn_f[(size_t)n * Dd + lane * 4] = make_float4(y0, y1, y2, y3);
    __half2 h01 = __floats2half2_rn(y0, y1);
    __half2 h23 = __floats2half2_rn(y2, y3);
    uint2 pk;
    pk.x = *(unsigned*)&h01;
    pk.y = *(unsigned*)&h23;
    *(uint2*)&g_rstn_h[(size_t)n * Dd + lane * 4] = pk;
}

// ---------------- launch ----------------
extern "C" void kernel_launch(void* const* d_in, const int* in_sizes, int n_in,
                              void* d_out, int out_size) {
    const float* feat  = (const float*)d_in[0];
    const int*   src   = (const int*)d_in[1];
    const int*   dst   = (const int*)d_in[2];
    const float* Wq    = (const float*)d_in[3];
    const float* bq    = (const float*)d_in[4];
    const float* Wk    = (const float*)d_in[5];
    const float* bk    = (const float*)d_in[6];
    const float* Wv    = (const float*)d_in[7];
    const float* bv    = (const float*)d_in[8];
    const float* ln_g  = (const float*)d_in[9];
    const float* ln_b  = (const float*)d_in[10];
    const float* W1    = (const float*)d_in[11];
    const float* b1    = (const float*)d_in[12];
    const float* alpha = (const float*)d_in[13];
    const float* W2    = (const float*)d_in[14];
    const float* b2    = (const float*)d_in[15];
    float* out = (float*)d_out;

    __half *pfh, *pwqkv, *pw1, *pw2, *prsth, *phid;
    float *pbqkv, *prstf;
    cudaGetSymbolAddress((void**)&pfh, g_feat_h);
    cudaGetSymbolAddress((void**)&pwqkv, g_wqkv_h);
    cudaGetSymbolAddress((void**)&pw1, g_w1h);
    cudaGetSymbolAddress((void**)&pw2, g_w2h);
    cudaGetSymbolAddress((void**)&pbqkv, g_bqkv);
    cudaGetSymbolAddress((void**)&prstf, g_rstn_f);
    cudaGetSymbolAddress((void**)&prsth, g_rstn_h);
    cudaGetSymbolAddress((void**)&phid, g_hid_h);

    const int MB = (Nn + 127) / 128;  // 782

    // side stream + fork/join events (created once; host-side resources only)
    static cudaStream_t s2 = nullptr;
    static cudaEvent_t evRoot = nullptr, evCsr = nullptr;
    if (s2 == nullptr) {
        cudaStreamCreateWithFlags(&s2, cudaStreamNonBlocking);
        cudaEventCreateWithFlags(&evRoot, cudaEventDisableTiming);
        cudaEventCreateWithFlags(&evCsr, cudaEventDisableTiming);
    }

    // fork: CSR chain on s2 (depends only on src/dst)
    cudaEventRecord(evRoot, 0);
    cudaStreamWaitEvent(s2, evRoot, 0);
    zero_deg<<<(Nn + 255) / 256, 256, 0, s2>>>();
    deg_count<<<(Ee + 255) / 256, 256, 0, s2>>>(dst);
    scanA<<<NBLK, 256, 0, s2>>>();
    scanB<<<1, 512, 0, s2>>>();
    scanC<<<(Nn + 255) / 256, 256, 0, s2>>>();
    scatter_k<<<(Ee + 255) / 256, 256, 0, s2>>>(src, dst);
    cudaEventRecord(evCsr, s2);

    // main chain: convert + QKV projection
    init_conv<<<(Nn * Dd + 255) / 256, 256>>>(feat, Wq, Wk, Wv, bq, bk, bv, W1, W2);
    gemm_h<4><<<dim3(QKV / 128, MB), 256>>>(pfh, pwqkv, pbqkv, nullptr, nullptr,
                                            nullptr, nullptr, nullptr, Nn, QKV, Dd);

    // join: pass_fused needs both qkv and CSR
    cudaStreamWaitEvent(0, evCsr, 0);
    pass_fused<<<(Nn + 3) / 4, 128>>>(feat, ln_g, ln_b);

    // FFN: [Nn,128]@[128,512] + PReLU -> fp16, then [Nn,512]@[512,128] + res + LN2 -> out
    gemm_h<1><<<dim3(Ff / 128, MB), 256>>>(prsth, pw1, b1, alpha, nullptr,
                                           nullptr, nullptr, phid, Nn, Ff, Dd);
    gemm_h<3><<<dim3(1, MB), 256>>>(phid, pw2, b2, nullptr, prstf,
                                    ln_g, ln_b, out, Nn, Dd, Ff);
}